// round 12
// baseline (speedup 1.0000x reference)
#include <cuda_runtime.h>
#include <cuda_fp16.h>

// ---------------------------------------------------------------------------
// GAT (2 layers, edge features, H=2 heads x C=16) + mean pool + MLP -> [G,2]
// Block-specialized fused kernel runs transform1 and CSR-histogram
// concurrently; accumulators re-zeroed at end of pipeline (load-time zeros
// cover the first call); dst-CSR atomic-free aggregation with fp16 feature
// rows; layer-2 transform fused into agg0 epilogue; pool fused into agg1.
// ---------------------------------------------------------------------------

#define MAXN 100352
#define MAXE 3211264
#define MAXG 256
#define NBS ((MAXN + 1023) / 1024)
#define HISTB 2048

__device__ __align__(16) uint2 g_h[MAXN * 8];       // layer-1 features, fp16x4
__device__ __align__(16) uint2 g_out[MAXN * 8];     // layer-2 features, fp16x4
__device__ __align__(16) float g_asrc[MAXN * 2];
__device__ __align__(16) float g_adst[MAXN * 2];
__device__ __align__(16) float g_asrc2[MAXN * 2];
__device__ __align__(16) float g_adst2[MAXN * 2];
__device__ __align__(16) int2  g_csr[MAXE];         // (src, ea_bits), dst-sorted
__device__ int g_rank[MAXE];
__device__ int g_rowptr[MAXN + 1];
__device__ int g_deg[MAXN];                          // zero at load & end of pass
__device__ int g_bsum[NBS];
__device__ int g_boff[NBS];
__device__ __align__(16) float g_scal[8];            // [0]=esum(acc) [1]=mean [2..5]=ce
__device__ __align__(16) float g_pool[MAXG * 32];    // zero at load & end of pass
__device__ float g_cnt[MAXG];                        // zero at load & end of pass

__device__ __forceinline__ int clampi(int v, int hi) {
    return v < 0 ? 0 : (v >= hi ? hi - 1 : v);
}

// ---------------------------------------------------------------------------
// fused: blocks [0, tb) -> layer-1 transform; blocks [tb, tb+HISTB) -> hist+esum
__global__ void __launch_bounds__(256)
k_fused(const float* __restrict__ xin, const float* __restrict__ W,
        const float* __restrict__ a_src, const float* __restrict__ a_dst,
        const int* __restrict__ ei, const float* __restrict__ ea,
        int n, int E, int tb) {
    __shared__ float W_sh[128 * 32];                 // 16 KB
    __shared__ float4 x4_sh[32][33];                 // 16.9 KB (padded)
    __shared__ float s_as[32], s_ad[32];
    __shared__ float sm_ps[8][32], sm_pd[8][32];
    __shared__ float red[256];
    int tid = threadIdx.x;

    if (blockIdx.x >= tb) {
        // ---------------- histogram + rank + edge_attr sum ----------------
        int bid = blockIdx.x - tb;
        float acc = 0.f;
        for (int e = bid * 256 + tid; e < E; e += HISTB * 256) {
            int d = clampi(ei[E + e], n);
            g_rank[e] = atomicAdd(&g_deg[d], 1);
            acc += ea[e];
        }
        red[tid] = acc;
        __syncthreads();
        for (int s = 128; s; s >>= 1) {
            if (tid < s) red[tid] += red[tid + s];
            __syncthreads();
        }
        if (tid == 0) atomicAdd(&g_scal[0], red[0]);
        return;
    }

    // ---------------- layer-1 transform: h = x @ W1 (fp16 store) ----------
    for (int i = tid; i < 128 * 32; i += 256) W_sh[i] = W[i];
    if (tid < 32) {
        s_as[tid] = a_src[tid];
        s_ad[tid] = a_dst[tid];
    }
    __syncthreads();
    int nb = blockIdx.x * 32;
    // stage x as float4: x4_sh[row][k'] = x[node][4k'..4k'+3]
    for (int i = tid; i < 32 * 32; i += 256) {
        int r = i >> 5, c4 = i & 31;
        int node = nb + r;
        float4 v = make_float4(0.f, 0.f, 0.f, 0.f);
        if (node < n)
            v = ((const float4*)(xin + (size_t)node * 128))[c4];
        x4_sh[r][c4] = v;
    }
    __syncthreads();

    int w = tid >> 5, lane = tid & 31;
    int node = nb + lane;
    float4 acc = make_float4(0.f, 0.f, 0.f, 0.f);
    const float4* W4 = (const float4*)W_sh;
    #pragma unroll 8
    for (int kq = 0; kq < 32; kq++) {
        float4 xv = x4_sh[lane][kq];                 // LDS.128 conflict-free
        float4 w0 = W4[(kq * 4 + 0) * 8 + w];        // broadcast LDS.128 x4
        float4 w1 = W4[(kq * 4 + 1) * 8 + w];
        float4 w2 = W4[(kq * 4 + 2) * 8 + w];
        float4 w3 = W4[(kq * 4 + 3) * 8 + w];
        acc.x = fmaf(xv.x, w0.x, acc.x); acc.y = fmaf(xv.x, w0.y, acc.y);
        acc.z = fmaf(xv.x, w0.z, acc.z); acc.w = fmaf(xv.x, w0.w, acc.w);
        acc.x = fmaf(xv.y, w1.x, acc.x); acc.y = fmaf(xv.y, w1.y, acc.y);
        acc.z = fmaf(xv.y, w1.z, acc.z); acc.w = fmaf(xv.y, w1.w, acc.w);
        acc.x = fmaf(xv.z, w2.x, acc.x); acc.y = fmaf(xv.z, w2.y, acc.y);
        acc.z = fmaf(xv.z, w2.z, acc.z); acc.w = fmaf(xv.z, w2.w, acc.w);
        acc.x = fmaf(xv.w, w3.x, acc.x); acc.y = fmaf(xv.w, w3.y, acc.y);
        acc.z = fmaf(xv.w, w3.z, acc.z); acc.w = fmaf(xv.w, w3.w, acc.w);
    }
    if (node < n) {
        union { __half2 h[2]; uint2 u; } pk;
        pk.h[0] = __floats2half2_rn(acc.x, acc.y);
        pk.h[1] = __floats2half2_rn(acc.z, acc.w);
        g_h[node * 8 + w] = pk.u;
    }

    sm_ps[w][lane] = acc.x * s_as[w * 4]     + acc.y * s_as[w * 4 + 1]
                   + acc.z * s_as[w * 4 + 2] + acc.w * s_as[w * 4 + 3];
    sm_pd[w][lane] = acc.x * s_ad[w * 4]     + acc.y * s_ad[w * 4 + 1]
                   + acc.z * s_ad[w * 4 + 2] + acc.w * s_ad[w * 4 + 3];
    __syncthreads();
    if (tid < 64) {
        int l = tid & 31, hh = tid >> 5;
        int node2 = nb + l;
        if (node2 < n) {
            int wb = hh * 4;
            float vs = sm_ps[wb][l] + sm_ps[wb + 1][l] + sm_ps[wb + 2][l] + sm_ps[wb + 3][l];
            float vd = sm_pd[wb][l] + sm_pd[wb + 1][l] + sm_pd[wb + 2][l] + sm_pd[wb + 3][l];
            g_asrc[node2 * 2 + hh] = vs;
            g_adst[node2 * 2 + hh] = vd;
        }
    }
}

// ---------------------------------------------------------------------------
__global__ void k_scan1(int n) {
    __shared__ int sm[1024];
    int t = threadIdx.x;
    int i = blockIdx.x * 1024 + t;
    int v = (i < n) ? g_deg[i] : 0;
    int x = v;
    sm[t] = x;
    __syncthreads();
    #pragma unroll
    for (int off = 1; off < 1024; off <<= 1) {
        int y = (t >= off) ? sm[t - off] : 0;
        __syncthreads();
        x += y;
        sm[t] = x;
        __syncthreads();
    }
    if (i < n) g_rowptr[i] = x - v;   // exclusive, pre-offset
    if (t == 1023) g_bsum[blockIdx.x] = x;
}

// scan2 + prep (edge coefficients + mean) folded in
__global__ void k_scan2p(int nb, const float* __restrict__ We1, const float* __restrict__ ae1,
                         const float* __restrict__ We2, const float* __restrict__ ae2, int E) {
    __shared__ int sm[1024];
    int t = threadIdx.x;
    if (t == 0) g_scal[1] = g_scal[0] / (float)E;
    if (t >= 4 && t < 8) {
        int tt = t - 4;
        int layer = tt >> 1, hh = tt & 1;
        const float* We = layer ? We2 : We1;
        const float* ae = layer ? ae2 : ae1;
        float c = 0.f;
        for (int i = 0; i < 16; i++) c += We[hh * 16 + i] * ae[hh * 16 + i];
        g_scal[2 + layer * 2 + hh] = c;
    }
    int v = (t < nb) ? g_bsum[t] : 0;
    int x = v;
    sm[t] = x;
    __syncthreads();
    #pragma unroll
    for (int off = 1; off < 1024; off <<= 1) {
        int y = (t >= off) ? sm[t - off] : 0;
        __syncthreads();
        x += y;
        sm[t] = x;
        __syncthreads();
    }
    if (t < nb) g_boff[t] = x - v;    // exclusive
}

// scan3 + deg re-zero (deg not needed after this point; restores state for
// the next graph replay; load-time zeros cover the first call)
__global__ void k_scan3z(int n, int E) {
    int i = blockIdx.x * blockDim.x + threadIdx.x;
    if (i < n) {
        g_rowptr[i] += g_boff[i >> 10];
        g_deg[i] = 0;
    }
    if (i == 0) g_rowptr[n] = E;
}

// atomic-free scatter: slot = rowptr[dst] + rank[e]
__global__ void k_scatter(const int* __restrict__ ei, const float* __restrict__ ea,
                          int E, int n) {
    for (int e = blockIdx.x * blockDim.x + threadIdx.x; e < E; e += gridDim.x * blockDim.x) {
        int s = clampi(ei[e], n);
        int d = clampi(ei[E + e], n);
        g_csr[g_rowptr[d] + g_rank[e]] = make_int2(s, __float_as_int(ea[e]));
    }
}

// ---------------------------------------------------------------------------
// fused aggregation: warp per dst node; 4 edges per gather iteration
// (four 8-lane groups); fp16 feature rows decoded to fp32 for accumulation.
// LAYER==0: features g_h/asrc/adst; epilogue = layer-2 transform -> g_out.
// LAYER==1: features g_out/asrc2/adst2; epilogue = mean-pool accumulation.
template <int LAYER>
__global__ void __launch_bounds__(256, 6)
k_agg(int n,
      const float* __restrict__ W2, const float* __restrict__ b1,
      const float* __restrict__ as2, const float* __restrict__ ad2,
      const int* __restrict__ batch, const float* __restrict__ b2,
      int G) {
    __shared__ float4 stage[8][32];
    __shared__ float W2s[32 * 32];
    __shared__ float b1s[32], as2s[32], ad2s[32];
    int tid = threadIdx.x;
    if (LAYER == 0) {
        for (int i = tid; i < 1024; i += 256) W2s[i] = W2[i];
        if (tid < 32) {
            b1s[tid] = b1[tid];
            as2s[tid] = as2[tid];
            ad2s[tid] = ad2[tid];
        }
        __syncthreads();
    }

    int wg = (blockIdx.x * blockDim.x + tid) >> 5;
    if (wg >= n) return;
    int w = tid >> 5, lane = tid & 31;
    int grp = lane >> 3;           // 4 groups of 8 lanes; group g takes edge t+g
    int q = lane & 7;              // lane-in-group owns columns 4q..4q+3
    int node = wg;
    float c0 = g_scal[2 + LAYER * 2];
    float c1 = g_scal[3 + LAYER * 2];
    float mean = g_scal[1];
    const uint2*  hf8  = LAYER ? g_out   : g_h;
    const float*  asrc = LAYER ? g_asrc2 : g_asrc;
    const float*  adst = LAYER ? g_adst2 : g_adst;
    float2 ad = ((const float2*)adst)[node];
    bool head1 = q >= 4;           // column quad's head (cols 16..31 -> head 1)

    float4 acc = make_float4(0.f, 0.f, 0.f, 0.f);
    float s0 = 0.f, s1 = 0.f;
    int beg = g_rowptr[node], end = g_rowptr[node + 1];

    for (int j0 = beg; j0 < end; j0 += 32) {
        int j = j0 + lane;
        bool v = j < end;
        int src = node;
        float av = 0.f;
        if (v) {
            int2 p = g_csr[j];
            src = p.x;
            av = __int_as_float(p.y);
        }
        float2 as = ((const float2*)asrc)[src];
        float a0 = as.x + ad.x + av * c0;
        float a1 = as.y + ad.y + av * c1;
        a0 = a0 > 0.f ? a0 : 0.2f * a0;
        a1 = a1 > 0.f ? a1 : 0.2f * a1;
        float ex0 = v ? __expf(a0) : 0.f;   // invalid lanes stage ex=0
        float ex1 = v ? __expf(a1) : 0.f;
        s0 += ex0;
        s1 += ex1;
        stage[w][lane] = make_float4(__int_as_float(src), ex0, ex1, 0.f);
        __syncwarp();
        int cnt = min(end - j0, 32);
        if (cnt == 32) {
            #pragma unroll
            for (int t = 0; t < 32; t += 4) {
                float4 p = stage[w][t + grp];
                union { uint2 u; __half2 h[2]; } pk;
                pk.u = hf8[__float_as_int(p.x) * 8 + q];   // 64B row per edge
                float2 f01 = __half22float2(pk.h[0]);
                float2 f23 = __half22float2(pk.h[1]);
                float e = head1 ? p.z : p.y;
                acc.x = fmaf(f01.x, e, acc.x);
                acc.y = fmaf(f01.y, e, acc.y);
                acc.z = fmaf(f23.x, e, acc.z);
                acc.w = fmaf(f23.y, e, acc.w);
            }
        } else {
            for (int t = 0; t < cnt; t += 4) {            // slots >= cnt carry ex=0
                float4 p = stage[w][t + grp];
                union { uint2 u; __half2 h[2]; } pk;
                pk.u = hf8[__float_as_int(p.x) * 8 + q];
                float2 f01 = __half22float2(pk.h[0]);
                float2 f23 = __half22float2(pk.h[1]);
                float e = head1 ? p.z : p.y;
                acc.x = fmaf(f01.x, e, acc.x);
                acc.y = fmaf(f01.y, e, acc.y);
                acc.z = fmaf(f23.x, e, acc.z);
                acc.w = fmaf(f23.y, e, acc.w);
            }
        }
        __syncwarp();
    }

    // combine the 4 groups (lanes q, q+8, q+16, q+24 hold the same columns)
    acc.x += __shfl_down_sync(0xffffffffu, acc.x, 16);
    acc.y += __shfl_down_sync(0xffffffffu, acc.y, 16);
    acc.z += __shfl_down_sync(0xffffffffu, acc.z, 16);
    acc.w += __shfl_down_sync(0xffffffffu, acc.w, 16);
    acc.x += __shfl_down_sync(0xffffffffu, acc.x, 8);
    acc.y += __shfl_down_sync(0xffffffffu, acc.y, 8);
    acc.z += __shfl_down_sync(0xffffffffu, acc.z, 8);
    acc.w += __shfl_down_sync(0xffffffffu, acc.w, 8);

    // self loop (src = node, ea = mean): add in lanes 0-7 after combine
    {
        float2 as = ((const float2*)asrc)[node];
        float a0 = as.x + ad.x + mean * c0;
        float a1 = as.y + ad.y + mean * c1;
        a0 = a0 > 0.f ? a0 : 0.2f * a0;
        a1 = a1 > 0.f ? a1 : 0.2f * a1;
        float ex0 = __expf(a0), ex1 = __expf(a1);
        if (lane == 0) { s0 += ex0; s1 += ex1; }
        union { uint2 u; __half2 h[2]; } pk;
        pk.u = hf8[node * 8 + q];
        float2 f01 = __half22float2(pk.h[0]);
        float2 f23 = __half22float2(pk.h[1]);
        float e = (lane < 8) ? (head1 ? ex1 : ex0) : 0.f;
        acc.x = fmaf(f01.x, e, acc.x);
        acc.y = fmaf(f01.y, e, acc.y);
        acc.z = fmaf(f23.x, e, acc.z);
        acc.w = fmaf(f23.y, e, acc.w);
    }

    #pragma unroll
    for (int off = 16; off; off >>= 1) {
        s0 += __shfl_xor_sync(0xffffffffu, s0, off);
        s1 += __shfl_xor_sync(0xffffffffu, s1, off);
    }
    float sinv = 1.f / ((head1 ? s1 : s0) + 1e-16f);
    float4 o4 = make_float4(acc.x * sinv, acc.y * sinv, acc.z * sinv, acc.w * sinv);
    // o4 valid in lanes 0-7 (columns 4q..4q+3)

    if (LAYER == 0) {
        // fused layer-2 transform: x2 = relu(o + b1); h2 = x2 @ W2 (fp32 math)
        float* xrow = (float*)&stage[w][0];
        if (lane < 8) {
            xrow[4 * q]     = fmaxf(o4.x + b1s[4 * q], 0.f);
            xrow[4 * q + 1] = fmaxf(o4.y + b1s[4 * q + 1], 0.f);
            xrow[4 * q + 2] = fmaxf(o4.z + b1s[4 * q + 2], 0.f);
            xrow[4 * q + 3] = fmaxf(o4.w + b1s[4 * q + 3], 0.f);
        }
        __syncwarp();
        float acc2 = 0.f;
        #pragma unroll 8
        for (int k = 0; k < 32; k++)
            acc2 = fmaf(xrow[k], W2s[k * 32 + lane], acc2);
        // store h2 row as fp16 (pairs from even lanes)
        float nbv = __shfl_down_sync(0xffffffffu, acc2, 1);
        if ((lane & 1) == 0) {
            __half2 hv = __floats2half2_rn(acc2, nbv);
            ((unsigned*)g_out)[node * 16 + (lane >> 1)] = *(unsigned*)&hv;
        }
        float ps = acc2 * as2s[lane];
        float pd = acc2 * ad2s[lane];
        #pragma unroll
        for (int off = 8; off; off >>= 1) {
            ps += __shfl_down_sync(0xffffffffu, ps, off, 16);
            pd += __shfl_down_sync(0xffffffffu, pd, off, 16);
        }
        if ((lane & 15) == 0) {
            int hh = lane >> 4;
            g_asrc2[node * 2 + hh] = ps;
            g_adst2[node * 2 + hh] = pd;
        }
    } else {
        int g = clampi(batch[node], G);
        if (lane < 8) {
            float4 add = make_float4(o4.x + b2[4 * q],     o4.y + b2[4 * q + 1],
                                     o4.z + b2[4 * q + 2], o4.w + b2[4 * q + 3]);
            atomicAdd((float4*)&g_pool[g * 32 + 4 * q], add);
        }
        if (lane == 0) atomicAdd(&g_cnt[g], 1.f);
    }
}

// ---------------------------------------------------------------------------
// MLP head + accumulator cleanup for the next pipeline pass (deterministic:
// each thread zeroes exactly the accumulators it consumed).
__global__ void k_mlp(float* __restrict__ out,
                      const float* __restrict__ Wf1, const float* __restrict__ bf1,
                      const float* __restrict__ Wf2, const float* __restrict__ bf2, int G) {
    int g = blockIdx.x * blockDim.x + threadIdx.x;
    if (g >= G) return;
    float cnt = g_cnt[g];
    float inv = 1.f / fmaxf(cnt, 1.f);
    float emb[32];
    #pragma unroll
    for (int i = 0; i < 32; i++) {
        emb[i] = g_pool[g * 32 + i] * inv;
        g_pool[g * 32 + i] = 0.f;        // restore for next replay
    }
    g_cnt[g] = 0.f;
    if (g == 0) g_scal[0] = 0.f;
    float o0 = bf2[0], o1 = bf2[1];
    for (int j = 0; j < 32; j++) {
        float z = bf1[j];
        #pragma unroll
        for (int i = 0; i < 32; i++) z = fmaf(emb[i], Wf1[i * 32 + j], z);
        z = fmaxf(z, 0.f);
        o0 = fmaf(z, Wf2[j * 2], o0);
        o1 = fmaf(z, Wf2[j * 2 + 1], o1);
    }
    out[g * 2] = o0;
    out[g * 2 + 1] = o1;
}

// ---------------------------------------------------------------------------
extern "C" void kernel_launch(void* const* d_in, const int* in_sizes, int n_in,
                              void* d_out, int out_size) {
    const float* x     = (const float*)d_in[0];
    const int*   ei    = (const int*)d_in[1];
    const float* ea    = (const float*)d_in[2];
    const int*   batch = (const int*)d_in[3];
    const float* W1  = (const float*)d_in[4];
    const float* as1 = (const float*)d_in[5];
    const float* ad1 = (const float*)d_in[6];
    const float* We1 = (const float*)d_in[7];
    const float* ae1 = (const float*)d_in[8];
    const float* b1  = (const float*)d_in[9];
    const float* W2  = (const float*)d_in[10];
    const float* as2 = (const float*)d_in[11];
    const float* ad2 = (const float*)d_in[12];
    const float* We2 = (const float*)d_in[13];
    const float* ae2 = (const float*)d_in[14];
    const float* b2  = (const float*)d_in[15];
    const float* Wf1 = (const float*)d_in[16];
    const float* bf1 = (const float*)d_in[17];
    const float* Wf2 = (const float*)d_in[18];
    const float* bf2 = (const float*)d_in[19];

    int N = in_sizes[0] / 128;
    int E = in_sizes[1] / 2;
    int G = out_size / 2;
    int nb = (N + 1023) / 1024;
    int tb = (N + 31) / 32;
    int ab = (N + 7) / 8;

    // transform1 and CSR histogram run concurrently (block-specialized)
    k_fused<<<tb + HISTB, 256>>>(x, W1, as1, ad1, ei, ea, N, E, tb);

    k_scan1<<<nb, 1024>>>(N);
    k_scan2p<<<1, 1024>>>(nb, We1, ae1, We2, ae2, E);
    k_scan3z<<<(N + 1023) / 1024, 1024>>>(N, E);
    k_scatter<<<2048, 512>>>(ei, ea, E, N);

    // agg0 (with fused layer-2 transform epilogue), then agg1 (fused pool)
    k_agg<0><<<ab, 256>>>(N, W2, b1, as2, ad2, nullptr, nullptr, G);
    k_agg<1><<<ab, 256>>>(N, nullptr, nullptr, nullptr, nullptr, batch, b2, G);

    k_mlp<<<1, 64>>>((float*)d_out, Wf1, bf1, Wf2, bf2, G);
}